// round 3
// baseline (speedup 1.0000x reference)
#include <cuda_runtime.h>
#include <cuda_bf16.h>
#include <cstdint>

typedef unsigned long long ull;

#define BSZ   256
#define LSEQ  2048
#define DD    128   // DIN == DOUT == 128

// ---------------------------------------------------------------------------
// Scratch for the three x-projections (U includes u_b, Gx includes g_b).
// __device__ globals: the sanctioned alloc-free scratch mechanism.
// ---------------------------------------------------------------------------
__device__ float d_U [BSZ * LSEQ * DD];
__device__ float d_Gx[BSZ * LSEQ * DD];
__device__ float d_Ax[BSZ * LSEQ * DD];

// ---------------------------------------------------------------------------
// f32x2 helpers (FFMA2: 2 fp32 FMA per instruction on sm_103a)
// ---------------------------------------------------------------------------
__device__ __forceinline__ ull pk2(float x, float y) {
    ull r;
    asm("mov.b64 %0, {%1, %2};" : "=l"(r) : "f"(x), "f"(y));
    return r;
}
__device__ __forceinline__ float2 upk2(ull v) {
    float2 f;
    asm("mov.b64 {%0, %1}, %2;" : "=f"(f.x), "=f"(f.y) : "l"(v));
    return f;
}
__device__ __forceinline__ ull ffma2(ull a, ull b, ull c) {
    ull d;
    asm("fma.rn.f32x2 %0, %1, %2, %3;" : "=l"(d) : "l"(a), "l"(b), "l"(c));
    return d;
}

__device__ __forceinline__ float tanhf_fast(float x) {
    float ax = fabsf(x);
    float e  = __expf(-2.0f * ax);
    float r  = __fdividef(1.0f - e, 1.0f + e);
    return copysignf(r, x);
}

// ---------------------------------------------------------------------------
// Projection GEMM: C[row, o] = sum_d x[row, d] * W[o, d]  (+ bias)
//   row = b*L + t  (x is row-major [B*L, 128])
//   blockIdx.y selects the matrix: 0 -> u_w (pitch 128, +u_b)
//                                  1 -> g_w[:, :128] (pitch 256, +g_b)
//                                  2 -> a_w[:, :128] (pitch 256, no bias)
// Tile: 128(M) x 128(N) x 128(K), 256 threads, 8x8 micro-tile,
// K packed in f32x2 pairs. B tile XOR-swizzled for conflict-free LDS.64.
// ---------------------------------------------------------------------------
__global__ void __launch_bounds__(256, 1)
rwa_proj_kernel(const float* __restrict__ x,
                const float* __restrict__ u_w,
                const float* __restrict__ u_b,
                const float* __restrict__ g_w,
                const float* __restrict__ g_b,
                const float* __restrict__ a_w)
{
    extern __shared__ ull smem[];
    ull* Asm = smem;          // [128][64] float2 : Asm[m*64 + k2]
    ull* Bsm = smem + 8192;   // [128][64] float2 : Bsm[n*64 + (k2 ^ (n&15))]

    const int tid = threadIdx.x;
    const int tx  = tid & 15;     // -> n = tx + jj*16
    const int ty  = tid >> 4;     // -> m = ty + ii*16
    const int nt  = blockIdx.y;
    const int row0 = blockIdx.x * 128;

    const float* wsrc = (nt == 0) ? u_w : (nt == 1) ? g_w : a_w;
    const int    wpitch = (nt == 0) ? 128 : 256;

    // ---- load A tile (x rows), store as float2 pairs along K ----
    {
        const float4* xp = (const float4*)(x + (size_t)row0 * DD);
        #pragma unroll
        for (int i = 0; i < 16; i++) {
            int idx = tid + i * 256;
            int r  = idx >> 5;
            int c4 = idx & 31;           // float4 index within row
            float4 v = xp[(size_t)r * 32 + c4];
            Asm[r * 64 + c4 * 2    ] = pk2(v.x, v.y);
            Asm[r * 64 + c4 * 2 + 1] = pk2(v.z, v.w);
        }
    }
    // ---- load B tile (weights), swizzled ----
    {
        #pragma unroll
        for (int i = 0; i < 16; i++) {
            int idx = tid + i * 256;
            int n  = idx >> 5;
            int c4 = idx & 31;
            const float4* wp = (const float4*)(wsrc + (size_t)n * wpitch);
            float4 v = wp[c4];
            int sw = n & 15;
            Bsm[n * 64 + ((c4 * 2    ) ^ sw)] = pk2(v.x, v.y);
            Bsm[n * 64 + ((c4 * 2 + 1) ^ sw)] = pk2(v.z, v.w);
        }
    }
    __syncthreads();

    ull acc[8][8];
    #pragma unroll
    for (int ii = 0; ii < 8; ii++)
        #pragma unroll
        for (int jj = 0; jj < 8; jj++) acc[ii][jj] = 0ull;

    #pragma unroll 4
    for (int k2 = 0; k2 < 64; k2++) {
        ull af[8], bf[8];
        #pragma unroll
        for (int ii = 0; ii < 8; ii++)
            af[ii] = Asm[(ty + ii * 16) * 64 + k2];
        #pragma unroll
        for (int jj = 0; jj < 8; jj++)
            bf[jj] = Bsm[(tx + jj * 16) * 64 + (k2 ^ tx)];
        #pragma unroll
        for (int ii = 0; ii < 8; ii++)
            #pragma unroll
            for (int jj = 0; jj < 8; jj++)
                acc[ii][jj] = ffma2(af[ii], bf[jj], acc[ii][jj]);
    }

    // ---- epilogue: bias + store ----
    float bias[8];
    #pragma unroll
    for (int jj = 0; jj < 8; jj++) {
        int n = tx + jj * 16;
        bias[jj] = (nt == 0) ? u_b[n] : (nt == 1) ? g_b[n] : 0.0f;
    }
    float* dst = (nt == 0) ? d_U : (nt == 1) ? d_Gx : d_Ax;

    #pragma unroll
    for (int ii = 0; ii < 8; ii++) {
        size_t rbase = (size_t)(row0 + ty + ii * 16) * DD;
        #pragma unroll
        for (int jj = 0; jj < 8; jj++) {
            float2 s = upk2(acc[ii][jj]);
            dst[rbase + tx + jj * 16] = s.x + s.y + bias[jj];
        }
    }
}

// ---------------------------------------------------------------------------
// Recurrent kernel: 128 CTAs x 512 threads; CTA handles batches (2*bid, 2*bid+1).
// Thread (o = tid&127, q = tid>>7) holds g_wh[o][32q..32q+31] and
// a_wh[o][...] in registers; per step computes partial h-matvecs for both
// batches, reduces via smem; threads tid<256 run the activation epilogue
// holding (num, den, a_max) in registers, prefetching U/Gx/Ax one step ahead.
// ---------------------------------------------------------------------------
__global__ void __launch_bounds__(512, 1)
rwa_rec_kernel(const float* __restrict__ g_w,
               const float* __restrict__ a_w,
               const float* __restrict__ s0,
               float* __restrict__ out)
{
    __shared__ ull   hsm[2 * 64];          // h as float2 pairs: [b][64]
    __shared__ float partG[4 * 2 * DD];    // [q][b][o]
    __shared__ float partA[4 * 2 * DD];

    const int tid = threadIdx.x;
    const int o   = tid & 127;
    const int q   = tid >> 7;

    // h-recurrence weights (cols 128..255 of g_w / a_w), in registers
    ull wg[16], wa[16];
    {
        const ull* gp = (const ull*)(g_w + (size_t)o * 256 + 128 + q * 32);
        const ull* ap = (const ull*)(a_w + (size_t)o * 256 + 128 + q * 32);
        #pragma unroll
        for (int j = 0; j < 16; j++) { wg[j] = gp[j]; wa[j] = ap[j]; }
    }

    const int eb = tid >> 7;   // epilogue batch (valid when tid < 256)
    const int eo = o;
    float num = 0.0f, den = 0.0f, amax = 1e-38f;
    size_t idx0 = ((size_t)(blockIdx.x * 2 + eb)) * LSEQ * DD + eo;
    float u_n = 0.0f, gx_n = 0.0f, ax_n = 0.0f;

    if (tid < 256) {
        ((float*)hsm)[eb * DD + eo] = tanhf_fast(s0[eo]);
        u_n  = d_U [idx0];
        gx_n = d_Gx[idx0];
        ax_n = d_Ax[idx0];
    }
    __syncthreads();

    const ull* h0p = hsm + q * 16;        // batch 0, this thread's d-quarter
    const ull* h1p = hsm + 64 + q * 16;   // batch 1

    for (int t = 0; t < LSEQ; t++) {
        // ---- h-matvec partials (all 512 threads, both batches) ----
        ull aG0 = 0ull, aA0 = 0ull, aG1 = 0ull, aA1 = 0ull;
        #pragma unroll
        for (int j = 0; j < 16; j++) {
            ull h0 = h0p[j];
            ull h1 = h1p[j];
            aG0 = ffma2(wg[j], h0, aG0);
            aA0 = ffma2(wa[j], h0, aA0);
            aG1 = ffma2(wg[j], h1, aG1);
            aA1 = ffma2(wa[j], h1, aA1);
        }
        {
            float2 s;
            s = upk2(aG0); partG[q * 256 +       o] = s.x + s.y;
            s = upk2(aG1); partG[q * 256 + 128 + o] = s.x + s.y;
            s = upk2(aA0); partA[q * 256 +       o] = s.x + s.y;
            s = upk2(aA1); partA[q * 256 + 128 + o] = s.x + s.y;
        }
        __syncthreads();

        // ---- activation epilogue (256 threads: one per (b, o)) ----
        if (tid < 256) {
            int pb = eb * DD + eo;
            float sumG = partG[pb] + partG[256 + pb] + partG[512 + pb] + partG[768 + pb];
            float sumA = partA[pb] + partA[256 + pb] + partA[512 + pb] + partA[768 + pb];

            float u = u_n, gx = gx_n, ax = ax_n;
            if (t + 1 < LSEQ) {                       // prefetch next step
                size_t id = idx0 + (size_t)(t + 1) * DD;
                u_n  = d_U [id];
                gx_n = d_Gx[id];
                ax_n = d_Ax[id];
            }

            float g  = tanhf_fast(gx + sumG);
            float z  = u * g;
            float a  = ax + sumA;
            float am = fmaxf(a, amax);
            float e  = __expf(am - amax);
            amax = am;
            num  = fmaf(z, e, num);
            den += e;
            float h = tanhf_fast(__fdividef(num, den));

            ((float*)hsm)[eb * DD + eo] = h;
            out[idx0 + (size_t)t * DD] = h;
        }
        __syncthreads();
    }
}

// ---------------------------------------------------------------------------
// kernel_launch
// Input order (metadata): 0:x  1:s0  2:u_w  3:u_b  4:g_w  5:g_b  6:a_w
// ---------------------------------------------------------------------------
extern "C" void kernel_launch(void* const* d_in, const int* in_sizes, int n_in,
                              void* d_out, int out_size)
{
    const float* x   = (const float*)d_in[0];
    const float* s0  = (const float*)d_in[1];
    const float* u_w = (const float*)d_in[2];
    const float* u_b = (const float*)d_in[3];
    const float* g_w = (const float*)d_in[4];
    const float* g_b = (const float*)d_in[5];
    const float* a_w = (const float*)d_in[6];
    float* out = (float*)d_out;

    cudaFuncSetAttribute(rwa_proj_kernel,
                         cudaFuncAttributeMaxDynamicSharedMemorySize, 131072);

    dim3 pgrid((BSZ * LSEQ) / 128, 3, 1);
    rwa_proj_kernel<<<pgrid, 256, 131072>>>(x, u_w, u_b, g_w, g_b, a_w);

    rwa_rec_kernel<<<BSZ / 2, 512>>>(g_w, a_w, s0, out);
}

// round 4
// speedup vs baseline: 1.1495x; 1.1495x over previous
#include <cuda_runtime.h>
#include <cuda_bf16.h>
#include <cstdint>

typedef unsigned long long ull;

#define BSZ   256
#define LSEQ  2048
#define DD    128   // DIN == DOUT == 128

// ---------------------------------------------------------------------------
// Scratch for the three x-projections (U includes u_b, Gx includes g_b).
// ---------------------------------------------------------------------------
__device__ float d_U [BSZ * LSEQ * DD];
__device__ float d_Gx[BSZ * LSEQ * DD];
__device__ float d_Ax[BSZ * LSEQ * DD];

// ---------------------------------------------------------------------------
// f32x2 helpers (FFMA2: 2 fp32 FMA per instruction on sm_103a)
// ---------------------------------------------------------------------------
__device__ __forceinline__ ull pk2(float x, float y) {
    ull r;
    asm("mov.b64 %0, {%1, %2};" : "=l"(r) : "f"(x), "f"(y));
    return r;
}
__device__ __forceinline__ float2 upk2(ull v) {
    float2 f;
    asm("mov.b64 {%0, %1}, %2;" : "=f"(f.x), "=f"(f.y) : "l"(v));
    return f;
}
__device__ __forceinline__ ull ffma2(ull a, ull b, ull c) {
    ull d;
    asm("fma.rn.f32x2 %0, %1, %2, %3;" : "=l"(d) : "l"(a), "l"(b), "l"(c));
    return d;
}

__device__ __forceinline__ float tanhf_fast(float x) {
    float ax = fabsf(x);
    float e  = __expf(-2.0f * ax);
    float r  = __fdividef(1.0f - e, 1.0f + e);
    return copysignf(r, x);
}

// ---------------------------------------------------------------------------
// Projection GEMM (unchanged from passing round): C[row,o] = x[row,:]·W[o,:]+b
// ---------------------------------------------------------------------------
__global__ void __launch_bounds__(256, 1)
rwa_proj_kernel(const float* __restrict__ x,
                const float* __restrict__ u_w,
                const float* __restrict__ u_b,
                const float* __restrict__ g_w,
                const float* __restrict__ g_b,
                const float* __restrict__ a_w)
{
    extern __shared__ ull smem[];
    ull* Asm = smem;          // [128][64] float2 : Asm[m*64 + k2]
    ull* Bsm = smem + 8192;   // [128][64] float2 : Bsm[n*64 + (k2 ^ (n&15))]

    const int tid = threadIdx.x;
    const int tx  = tid & 15;     // -> n = tx + jj*16
    const int ty  = tid >> 4;     // -> m = ty + ii*16
    const int nt  = blockIdx.y;
    const int row0 = blockIdx.x * 128;

    const float* wsrc = (nt == 0) ? u_w : (nt == 1) ? g_w : a_w;
    const int    wpitch = (nt == 0) ? 128 : 256;

    {
        const float4* xp = (const float4*)(x + (size_t)row0 * DD);
        #pragma unroll
        for (int i = 0; i < 16; i++) {
            int idx = tid + i * 256;
            int r  = idx >> 5;
            int c4 = idx & 31;
            float4 v = xp[(size_t)r * 32 + c4];
            Asm[r * 64 + c4 * 2    ] = pk2(v.x, v.y);
            Asm[r * 64 + c4 * 2 + 1] = pk2(v.z, v.w);
        }
    }
    {
        #pragma unroll
        for (int i = 0; i < 16; i++) {
            int idx = tid + i * 256;
            int n  = idx >> 5;
            int c4 = idx & 31;
            const float4* wp = (const float4*)(wsrc + (size_t)n * wpitch);
            float4 v = wp[c4];
            int sw = n & 15;
            Bsm[n * 64 + ((c4 * 2    ) ^ sw)] = pk2(v.x, v.y);
            Bsm[n * 64 + ((c4 * 2 + 1) ^ sw)] = pk2(v.z, v.w);
        }
    }
    __syncthreads();

    ull acc[8][8];
    #pragma unroll
    for (int ii = 0; ii < 8; ii++)
        #pragma unroll
        for (int jj = 0; jj < 8; jj++) acc[ii][jj] = 0ull;

    #pragma unroll 4
    for (int k2 = 0; k2 < 64; k2++) {
        ull af[8], bf[8];
        #pragma unroll
        for (int ii = 0; ii < 8; ii++)
            af[ii] = Asm[(ty + ii * 16) * 64 + k2];
        #pragma unroll
        for (int jj = 0; jj < 8; jj++)
            bf[jj] = Bsm[(tx + jj * 16) * 64 + (k2 ^ tx)];
        #pragma unroll
        for (int ii = 0; ii < 8; ii++)
            #pragma unroll
            for (int jj = 0; jj < 8; jj++)
                acc[ii][jj] = ffma2(af[ii], bf[jj], acc[ii][jj]);
    }

    float bias[8];
    #pragma unroll
    for (int jj = 0; jj < 8; jj++) {
        int n = tx + jj * 16;
        bias[jj] = (nt == 0) ? u_b[n] : (nt == 1) ? g_b[n] : 0.0f;
    }
    float* dst = (nt == 0) ? d_U : (nt == 1) ? d_Gx : d_Ax;

    #pragma unroll
    for (int ii = 0; ii < 8; ii++) {
        size_t rbase = (size_t)(row0 + ty + ii * 16) * DD;
        #pragma unroll
        for (int jj = 0; jj < 8; jj++) {
            float2 s = upk2(acc[ii][jj]);
            dst[rbase + tx + jj * 16] = s.x + s.y + bias[jj];
        }
    }
}

// ---------------------------------------------------------------------------
// Recurrent kernel v2: 128 CTAs x 512 threads, CTA = batches (2i, 2i+1).
//
// Thread layout: o = tid>>2 (output channel), q = tid&3 (K-quarter).
// The 4 q-partials of each o live in ONE warp -> shfl_xor butterfly reduce
// (no smem round-trip, no reduction barrier). h double-buffered in smem with
// padded stride-17 (ull) chunks so the q-broadcast LDS.64 is conflict-free.
// Every lane runs the epilogue for batch (q&1): all warps do identical work,
// half the MUFU issues, one __syncthreads per step total.
// ---------------------------------------------------------------------------
__global__ void __launch_bounds__(512, 1)
rwa_rec_kernel(const float* __restrict__ g_w,
               const float* __restrict__ a_w,
               const float* __restrict__ s0,
               float* __restrict__ out)
{
    // [buf][batch][68 ull]: 4 chunks of 16 ull + 1 pad ull each (stride 17)
    __shared__ ull hsm[2][2][68];

    const int tid = threadIdx.x;
    const int o   = tid >> 2;
    const int q   = tid & 3;
    const int mb  = q & 1;          // batch this lane's epilogue handles

    // h-recurrence weights (cols 128..255 of g_w / a_w), in registers
    ull wg[16], wa[16];
    {
        const ull* gp = (const ull*)(g_w + (size_t)o * 256 + 128 + q * 32);
        const ull* ap = (const ull*)(a_w + (size_t)o * 256 + 128 + q * 32);
        #pragma unroll
        for (int j = 0; j < 16; j++) { wg[j] = gp[j]; wa[j] = ap[j]; }
    }

    // epilogue state for batch mb
    float num = 0.0f, den = 0.0f, amax = 1e-38f;
    const size_t idx0 = ((size_t)(blockIdx.x * 2 + mb)) * LSEQ * DD + o;
    const int fo = ((o >> 5) * 34) + (o & 31);   // padded float offset of h[o]

    // init h(-1) = tanh(s0) into buffer 0 (same for both batches)
    if (q < 2) {
        float h0 = tanhf_fast(s0[o]);
        ((float*)&hsm[0][mb][0])[fo] = h0;
    }
    // current-step (t=0) inputs
    float cu = d_U[idx0], cg = d_Gx[idx0], ca = d_Ax[idx0];
    __syncthreads();

    for (int t = 0; t < LSEQ; t++) {
        // prefetch t+1 inputs (independent of h -> overlaps matvec + barrier)
        float nu = 0.0f, ng = 0.0f, na = 0.0f;
        if (t + 1 < LSEQ) {
            size_t id = idx0 + (size_t)(t + 1) * DD;
            nu = d_U[id]; ng = d_Gx[id]; na = d_Ax[id];
        }

        // ---- h-matvec partials: both batches, this thread's K-quarter ----
        const ull* h0p = &hsm[t & 1][0][q * 17];
        const ull* h1p = &hsm[t & 1][1][q * 17];
        ull aG0 = 0ull, aA0 = 0ull, aG1 = 0ull, aA1 = 0ull;
        #pragma unroll
        for (int j = 0; j < 16; j++) {
            ull h0 = h0p[j];
            ull h1 = h1p[j];
            aG0 = ffma2(wg[j], h0, aG0);
            aA0 = ffma2(wa[j], h0, aA0);
            aG1 = ffma2(wg[j], h1, aG1);
            aA1 = ffma2(wa[j], h1, aA1);
        }
        float2 s;
        s = upk2(aG0); float sG0 = s.x + s.y;
        s = upk2(aA0); float sA0 = s.x + s.y;
        s = upk2(aG1); float sG1 = s.x + s.y;
        s = upk2(aA1); float sA1 = s.x + s.y;

        // butterfly reduce over q (lanes differing in bits 0..1)
        sG0 += __shfl_xor_sync(0xffffffffu, sG0, 1);
        sA0 += __shfl_xor_sync(0xffffffffu, sA0, 1);
        sG1 += __shfl_xor_sync(0xffffffffu, sG1, 1);
        sA1 += __shfl_xor_sync(0xffffffffu, sA1, 1);
        sG0 += __shfl_xor_sync(0xffffffffu, sG0, 2);
        sA0 += __shfl_xor_sync(0xffffffffu, sA0, 2);
        sG1 += __shfl_xor_sync(0xffffffffu, sG1, 2);
        sA1 += __shfl_xor_sync(0xffffffffu, sA1, 2);

        // ---- epilogue: each lane handles batch mb = q&1 ----
        float sG = mb ? sG1 : sG0;
        float sA = mb ? sA1 : sA0;

        float g  = tanhf_fast(cg + sG);
        float z  = cu * g;
        float a  = ca + sA;
        float m  = fmaxf(a, amax);
        float e  = __expf(m - amax);
        amax = m;
        num  = fmaf(z, e, num);
        den += e;
        float h = tanhf_fast(__fdividef(num, den));

        if (q < 2) {
            ((float*)&hsm[(t + 1) & 1][mb][0])[fo] = h;
            out[idx0 + (size_t)t * DD] = h;
        }

        cu = nu; cg = ng; ca = na;
        __syncthreads();   // publish h(t) (buf (t+1)&1) for step t+1
    }
}

// ---------------------------------------------------------------------------
// kernel_launch
// Input order (metadata): 0:x  1:s0  2:u_w  3:u_b  4:g_w  5:g_b  6:a_w
// ---------------------------------------------------------------------------
extern "C" void kernel_launch(void* const* d_in, const int* in_sizes, int n_in,
                              void* d_out, int out_size)
{
    const float* x   = (const float*)d_in[0];
    const float* s0  = (const float*)d_in[1];
    const float* u_w = (const float*)d_in[2];
    const float* u_b = (const float*)d_in[3];
    const float* g_w = (const float*)d_in[4];
    const float* g_b = (const float*)d_in[5];
    const float* a_w = (const float*)d_in[6];
    float* out = (float*)d_out;

    cudaFuncSetAttribute(rwa_proj_kernel,
                         cudaFuncAttributeMaxDynamicSharedMemorySize, 131072);

    dim3 pgrid((BSZ * LSEQ) / 128, 3, 1);
    rwa_proj_kernel<<<pgrid, 256, 131072>>>(x, u_w, u_b, g_w, g_b, a_w);

    rwa_rec_kernel<<<BSZ / 2, 512>>>(g_w, a_w, s0, out);
}

// round 5
// speedup vs baseline: 1.1512x; 1.0015x over previous
#include <cuda_runtime.h>
#include <cuda_bf16.h>
#include <cstdint>

typedef unsigned long long ull;

#define BSZ   256
#define LSEQ  2048
#define DD    128   // DIN == DOUT == 128

// ---------------------------------------------------------------------------
// Scratch for the three x-projections (U includes u_b, Gx includes g_b).
// ---------------------------------------------------------------------------
__device__ float d_U [BSZ * LSEQ * DD];
__device__ float d_Gx[BSZ * LSEQ * DD];
__device__ float d_Ax[BSZ * LSEQ * DD];

// ---------------------------------------------------------------------------
// f32x2 helpers (FFMA2: 2 fp32 FMA per instruction on sm_103a)
// ---------------------------------------------------------------------------
__device__ __forceinline__ ull pk2(float x, float y) {
    ull r;
    asm("mov.b64 %0, {%1, %2};" : "=l"(r) : "f"(x), "f"(y));
    return r;
}
__device__ __forceinline__ float2 upk2(ull v) {
    float2 f;
    asm("mov.b64 {%0, %1}, %2;" : "=f"(f.x), "=f"(f.y) : "l"(v));
    return f;
}
__device__ __forceinline__ ull ffma2(ull a, ull b, ull c) {
    ull d;
    asm("fma.rn.f32x2 %0, %1, %2, %3;" : "=l"(d) : "l"(a), "l"(b), "l"(c));
    return d;
}

// HW tanh (MUFU.TANH, sm_75+): single instruction, ~2^-11 rel err.
__device__ __forceinline__ float tanh_hw(float x) {
    float r;
    asm("tanh.approx.f32 %0, %1;" : "=f"(r) : "f"(x));
    return r;
}

__device__ __forceinline__ float tanhf_fast(float x) {
    float ax = fabsf(x);
    float e  = __expf(-2.0f * ax);
    float r  = __fdividef(1.0f - e, 1.0f + e);
    return copysignf(r, x);
}

// ---------------------------------------------------------------------------
// Projection GEMM (unchanged, protected win): C[row,o] = x[row,:]·W[o,:]+b
// ---------------------------------------------------------------------------
__global__ void __launch_bounds__(256, 1)
rwa_proj_kernel(const float* __restrict__ x,
                const float* __restrict__ u_w,
                const float* __restrict__ u_b,
                const float* __restrict__ g_w,
                const float* __restrict__ g_b,
                const float* __restrict__ a_w)
{
    extern __shared__ ull smem[];
    ull* Asm = smem;          // [128][64] float2 : Asm[m*64 + k2]
    ull* Bsm = smem + 8192;   // [128][64] float2 : Bsm[n*64 + (k2 ^ (n&15))]

    const int tid = threadIdx.x;
    const int tx  = tid & 15;     // -> n = tx + jj*16
    const int ty  = tid >> 4;     // -> m = ty + ii*16
    const int nt  = blockIdx.y;
    const int row0 = blockIdx.x * 128;

    const float* wsrc = (nt == 0) ? u_w : (nt == 1) ? g_w : a_w;
    const int    wpitch = (nt == 0) ? 128 : 256;

    {
        const float4* xp = (const float4*)(x + (size_t)row0 * DD);
        #pragma unroll
        for (int i = 0; i < 16; i++) {
            int idx = tid + i * 256;
            int r  = idx >> 5;
            int c4 = idx & 31;
            float4 v = xp[(size_t)r * 32 + c4];
            Asm[r * 64 + c4 * 2    ] = pk2(v.x, v.y);
            Asm[r * 64 + c4 * 2 + 1] = pk2(v.z, v.w);
        }
    }
    {
        #pragma unroll
        for (int i = 0; i < 16; i++) {
            int idx = tid + i * 256;
            int n  = idx >> 5;
            int c4 = idx & 31;
            const float4* wp = (const float4*)(wsrc + (size_t)n * wpitch);
            float4 v = wp[c4];
            int sw = n & 15;
            Bsm[n * 64 + ((c4 * 2    ) ^ sw)] = pk2(v.x, v.y);
            Bsm[n * 64 + ((c4 * 2 + 1) ^ sw)] = pk2(v.z, v.w);
        }
    }
    __syncthreads();

    ull acc[8][8];
    #pragma unroll
    for (int ii = 0; ii < 8; ii++)
        #pragma unroll
        for (int jj = 0; jj < 8; jj++) acc[ii][jj] = 0ull;

    #pragma unroll 4
    for (int k2 = 0; k2 < 64; k2++) {
        ull af[8], bf[8];
        #pragma unroll
        for (int ii = 0; ii < 8; ii++)
            af[ii] = Asm[(ty + ii * 16) * 64 + k2];
        #pragma unroll
        for (int jj = 0; jj < 8; jj++)
            bf[jj] = Bsm[(tx + jj * 16) * 64 + (k2 ^ tx)];
        #pragma unroll
        for (int ii = 0; ii < 8; ii++)
            #pragma unroll
            for (int jj = 0; jj < 8; jj++)
                acc[ii][jj] = ffma2(af[ii], bf[jj], acc[ii][jj]);
    }

    float bias[8];
    #pragma unroll
    for (int jj = 0; jj < 8; jj++) {
        int n = tx + jj * 16;
        bias[jj] = (nt == 0) ? u_b[n] : (nt == 1) ? g_b[n] : 0.0f;
    }
    float* dst = (nt == 0) ? d_U : (nt == 1) ? d_Gx : d_Ax;

    #pragma unroll
    for (int ii = 0; ii < 8; ii++) {
        size_t rbase = (size_t)(row0 + ty + ii * 16) * DD;
        #pragma unroll
        for (int jj = 0; jj < 8; jj++) {
            float2 s = upk2(acc[ii][jj]);
            dst[rbase + tx + jj * 16] = s.x + s.y + bias[jj];
        }
    }
}

// ---------------------------------------------------------------------------
// Recurrent kernel v3: 128 CTAs x 512 threads, CTA = batches (2i, 2i+1).
// o = tid>>2, q = tid&3 (K-quarter), mb = q&1 (epilogue batch).
//  - h in smem as [buf][batch][chunk q][36 floats] (144B stride: LDS.128-
//    aligned, conflict-free chunk bases) -> 16 LDS.128/thread/step.
//  - 4-shfl reduction: shfl#1 exchanges the OTHER batch's partial between
//    mb-paired lanes, shfl#2 folds K-halves. Each lane ends with its own
//    batch's (sumG, sumA).
//  - MUFU tanh.approx for both tanh's -> short epilogue.
// ---------------------------------------------------------------------------
__global__ void __launch_bounds__(512, 1)
rwa_rec_kernel(const float* __restrict__ g_w,
               const float* __restrict__ a_w,
               const float* __restrict__ s0,
               float* __restrict__ out)
{
    __shared__ float hs[2][2][4][36];   // [buf][batch][chunk][32 + 4 pad]

    const int tid = threadIdx.x;
    const int o   = tid >> 2;
    const int q   = tid & 3;
    const int mb  = q & 1;          // batch this lane's epilogue handles

    // h-recurrence weights (cols 128..255 of g_w / a_w), in registers
    ull wg[16], wa[16];
    {
        const ull* gp = (const ull*)(g_w + (size_t)o * 256 + 128 + q * 32);
        const ull* ap = (const ull*)(a_w + (size_t)o * 256 + 128 + q * 32);
        #pragma unroll
        for (int j = 0; j < 16; j++) { wg[j] = gp[j]; wa[j] = ap[j]; }
    }

    // epilogue state for batch mb
    float num = 0.0f, den = 0.0f, amax = 1e-38f;
    const size_t idx0 = ((size_t)(blockIdx.x * 2 + mb)) * LSEQ * DD + o;

    // init h(-1) = tanh(s0) into buffer 0 (same value for both batches)
    if (q < 2) {
        hs[0][mb][o >> 5][o & 31] = tanhf_fast(s0[o]);
    }
    // current-step (t=0) inputs
    float cu = d_U[idx0], cg = d_Gx[idx0], ca = d_Ax[idx0];
    __syncthreads();

    for (int t = 0; t < LSEQ; t++) {
        // prefetch t+1 inputs (independent of h -> overlaps matvec + barrier)
        float nu = 0.0f, ng = 0.0f, na = 0.0f;
        if (t + 1 < LSEQ) {
            size_t id = idx0 + (size_t)(t + 1) * DD;
            nu = d_U[id]; ng = d_Gx[id]; na = d_Ax[id];
        }

        // ---- h-matvec partials: both batches, this thread's K-quarter ----
        const ulonglong2* h0p = (const ulonglong2*)&hs[t & 1][0][q][0];
        const ulonglong2* h1p = (const ulonglong2*)&hs[t & 1][1][q][0];
        ull aG0 = 0ull, aA0 = 0ull, aG1 = 0ull, aA1 = 0ull;
        #pragma unroll
        for (int j = 0; j < 8; j++) {
            ulonglong2 h0 = h0p[j];
            ulonglong2 h1 = h1p[j];
            aG0 = ffma2(wg[2*j  ], h0.x, aG0);
            aA0 = ffma2(wa[2*j  ], h0.x, aA0);
            aG1 = ffma2(wg[2*j  ], h1.x, aG1);
            aA1 = ffma2(wa[2*j  ], h1.x, aA1);
            aG0 = ffma2(wg[2*j+1], h0.y, aG0);
            aA0 = ffma2(wa[2*j+1], h0.y, aA0);
            aG1 = ffma2(wg[2*j+1], h1.y, aG1);
            aA1 = ffma2(wa[2*j+1], h1.y, aA1);
        }
        float2 s;
        s = upk2(aG0); float sG0 = s.x + s.y;
        s = upk2(aA0); float sA0 = s.x + s.y;
        s = upk2(aG1); float sG1 = s.x + s.y;
        s = upk2(aA1); float sA1 = s.x + s.y;

        // ---- reduction over q: 4 shfls total ----
        // step 1 (xor 1): exchange the OTHER batch's partial with mb-partner
        float sendG = mb ? sG0 : sG1;
        float sendA = mb ? sA0 : sA1;
        float rG = __shfl_xor_sync(0xffffffffu, sendG, 1);
        float rA = __shfl_xor_sync(0xffffffffu, sendA, 1);
        float myG = (mb ? sG1 : sG0) + rG;   // my batch, my K-half
        float myA = (mb ? sA1 : sA0) + rA;
        // step 2 (xor 2): fold K-halves (partner has same mb)
        myG += __shfl_xor_sync(0xffffffffu, myG, 2);
        myA += __shfl_xor_sync(0xffffffffu, myA, 2);

        // ---- epilogue (every lane, batch mb) ----
        float g  = tanh_hw(cg + myG);
        float z  = cu * g;
        float a  = ca + myA;
        float m  = fmaxf(a, amax);
        float e  = __expf(m - amax);
        amax = m;
        num  = fmaf(z, e, num);
        den += e;
        float h = tanh_hw(__fdividef(num, den));

        if (q < 2) {
            hs[(t + 1) & 1][mb][o >> 5][o & 31] = h;
            out[idx0 + (size_t)t * DD] = h;
        }

        cu = nu; cg = ng; ca = na;
        __syncthreads();   // publish h(t) for step t+1
    }
}

// ---------------------------------------------------------------------------
// kernel_launch
// Input order (metadata): 0:x  1:s0  2:u_w  3:u_b  4:g_w  5:g_b  6:a_w
// ---------------------------------------------------------------------------
extern "C" void kernel_launch(void* const* d_in, const int* in_sizes, int n_in,
                              void* d_out, int out_size)
{
    const float* x   = (const float*)d_in[0];
    const float* s0  = (const float*)d_in[1];
    const float* u_w = (const float*)d_in[2];
    const float* u_b = (const float*)d_in[3];
    const float* g_w = (const float*)d_in[4];
    const float* g_b = (const float*)d_in[5];
    const float* a_w = (const float*)d_in[6];
    float* out = (float*)d_out;

    cudaFuncSetAttribute(rwa_proj_kernel,
                         cudaFuncAttributeMaxDynamicSharedMemorySize, 131072);

    dim3 pgrid((BSZ * LSEQ) / 128, 3, 1);
    rwa_proj_kernel<<<pgrid, 256, 131072>>>(x, u_w, u_b, g_w, g_b, a_w);

    rwa_rec_kernel<<<BSZ / 2, 512>>>(g_w, a_w, s0, out);
}

// round 6
// speedup vs baseline: 1.1593x; 1.0071x over previous
#include <cuda_runtime.h>
#include <cuda_bf16.h>
#include <cstdint>

typedef unsigned long long ull;

#define BSZ   256
#define LSEQ  2048
#define DD    128   // DIN == DOUT == 128

// ---------------------------------------------------------------------------
// Scratch for the three x-projections (U includes u_b, Gx includes g_b).
// ---------------------------------------------------------------------------
__device__ float d_U [BSZ * LSEQ * DD];
__device__ float d_Gx[BSZ * LSEQ * DD];
__device__ float d_Ax[BSZ * LSEQ * DD];

// ---------------------------------------------------------------------------
// f32x2 helpers (FFMA2: 2 fp32 FMA per instruction on sm_103a)
// ---------------------------------------------------------------------------
__device__ __forceinline__ ull pk2(float x, float y) {
    ull r;
    asm("mov.b64 %0, {%1, %2};" : "=l"(r) : "f"(x), "f"(y));
    return r;
}
__device__ __forceinline__ float2 upk2(ull v) {
    float2 f;
    asm("mov.b64 {%0, %1}, %2;" : "=f"(f.x), "=f"(f.y) : "l"(v));
    return f;
}
__device__ __forceinline__ ull ffma2(ull a, ull b, ull c) {
    ull d;
    asm("fma.rn.f32x2 %0, %1, %2, %3;" : "=l"(d) : "l"(a), "l"(b), "l"(c));
    return d;
}

// HW tanh (MUFU.TANH, sm_75+): single instruction, ~2^-11 rel err.
__device__ __forceinline__ float tanh_hw(float x) {
    float r;
    asm("tanh.approx.f32 %0, %1;" : "=f"(r) : "f"(x));
    return r;
}

__device__ __forceinline__ float tanhf_fast(float x) {
    float ax = fabsf(x);
    float e  = __expf(-2.0f * ax);
    float r  = __fdividef(1.0f - e, 1.0f + e);
    return copysignf(r, x);
}

// ---------------------------------------------------------------------------
// Projection GEMM (unchanged, protected win): C[row,o] = x[row,:]·W[o,:]+b
// ---------------------------------------------------------------------------
__global__ void __launch_bounds__(256, 1)
rwa_proj_kernel(const float* __restrict__ x,
                const float* __restrict__ u_w,
                const float* __restrict__ u_b,
                const float* __restrict__ g_w,
                const float* __restrict__ g_b,
                const float* __restrict__ a_w)
{
    extern __shared__ ull smem[];
    ull* Asm = smem;          // [128][64] float2 : Asm[m*64 + k2]
    ull* Bsm = smem + 8192;   // [128][64] float2 : Bsm[n*64 + (k2 ^ (n&15))]

    const int tid = threadIdx.x;
    const int tx  = tid & 15;     // -> n = tx + jj*16
    const int ty  = tid >> 4;     // -> m = ty + ii*16
    const int nt  = blockIdx.y;
    const int row0 = blockIdx.x * 128;

    const float* wsrc = (nt == 0) ? u_w : (nt == 1) ? g_w : a_w;
    const int    wpitch = (nt == 0) ? 128 : 256;

    {
        const float4* xp = (const float4*)(x + (size_t)row0 * DD);
        #pragma unroll
        for (int i = 0; i < 16; i++) {
            int idx = tid + i * 256;
            int r  = idx >> 5;
            int c4 = idx & 31;
            float4 v = xp[(size_t)r * 32 + c4];
            Asm[r * 64 + c4 * 2    ] = pk2(v.x, v.y);
            Asm[r * 64 + c4 * 2 + 1] = pk2(v.z, v.w);
        }
    }
    {
        #pragma unroll
        for (int i = 0; i < 16; i++) {
            int idx = tid + i * 256;
            int n  = idx >> 5;
            int c4 = idx & 31;
            const float4* wp = (const float4*)(wsrc + (size_t)n * wpitch);
            float4 v = wp[c4];
            int sw = n & 15;
            Bsm[n * 64 + ((c4 * 2    ) ^ sw)] = pk2(v.x, v.y);
            Bsm[n * 64 + ((c4 * 2 + 1) ^ sw)] = pk2(v.z, v.w);
        }
    }
    __syncthreads();

    ull acc[8][8];
    #pragma unroll
    for (int ii = 0; ii < 8; ii++)
        #pragma unroll
        for (int jj = 0; jj < 8; jj++) acc[ii][jj] = 0ull;

    #pragma unroll 4
    for (int k2 = 0; k2 < 64; k2++) {
        ull af[8], bf[8];
        #pragma unroll
        for (int ii = 0; ii < 8; ii++)
            af[ii] = Asm[(ty + ii * 16) * 64 + k2];
        #pragma unroll
        for (int jj = 0; jj < 8; jj++)
            bf[jj] = Bsm[(tx + jj * 16) * 64 + (k2 ^ tx)];
        #pragma unroll
        for (int ii = 0; ii < 8; ii++)
            #pragma unroll
            for (int jj = 0; jj < 8; jj++)
                acc[ii][jj] = ffma2(af[ii], bf[jj], acc[ii][jj]);
    }

    float bias[8];
    #pragma unroll
    for (int jj = 0; jj < 8; jj++) {
        int n = tx + jj * 16;
        bias[jj] = (nt == 0) ? u_b[n] : (nt == 1) ? g_b[n] : 0.0f;
    }
    float* dst = (nt == 0) ? d_U : (nt == 1) ? d_Gx : d_Ax;

    #pragma unroll
    for (int ii = 0; ii < 8; ii++) {
        size_t rbase = (size_t)(row0 + ty + ii * 16) * DD;
        #pragma unroll
        for (int jj = 0; jj < 8; jj++) {
            float2 s = upk2(acc[ii][jj]);
            dst[rbase + tx + jj * 16] = s.x + s.y + bias[jj];
        }
    }
}

// ---------------------------------------------------------------------------
// Recurrent kernel v3: 128 CTAs x 512 threads, CTA = batches (2i, 2i+1).
// o = tid>>2, q = tid&3 (K-quarter), mb = q&1 (epilogue batch).
//  - h in smem as [buf][batch][chunk q][36 floats] (144B stride: LDS.128-
//    aligned, conflict-free chunk bases) -> 16 LDS.128/thread/step.
//  - 4-shfl reduction: shfl#1 exchanges the OTHER batch's partial between
//    mb-paired lanes, shfl#2 folds K-halves. Each lane ends with its own
//    batch's (sumG, sumA).
//  - MUFU tanh.approx for both tanh's -> short epilogue.
// ---------------------------------------------------------------------------
__global__ void __launch_bounds__(512, 1)
rwa_rec_kernel(const float* __restrict__ g_w,
               const float* __restrict__ a_w,
               const float* __restrict__ s0,
               float* __restrict__ out)
{
    __shared__ float hs[2][2][4][36];   // [buf][batch][chunk][32 + 4 pad]

    const int tid = threadIdx.x;
    const int o   = tid >> 2;
    const int q   = tid & 3;
    const int mb  = q & 1;          // batch this lane's epilogue handles

    // h-recurrence weights (cols 128..255 of g_w / a_w), in registers
    ull wg[16], wa[16];
    {
        const ull* gp = (const ull*)(g_w + (size_t)o * 256 + 128 + q * 32);
        const ull* ap = (const ull*)(a_w + (size_t)o * 256 + 128 + q * 32);
        #pragma unroll
        for (int j = 0; j < 16; j++) { wg[j] = gp[j]; wa[j] = ap[j]; }
    }

    // epilogue state for batch mb
    float num = 0.0f, den = 0.0f, amax = 1e-38f;
    const size_t idx0 = ((size_t)(blockIdx.x * 2 + mb)) * LSEQ * DD + o;

    // init h(-1) = tanh(s0) into buffer 0 (same value for both batches)
    if (q < 2) {
        hs[0][mb][o >> 5][o & 31] = tanhf_fast(s0[o]);
    }
    // current-step (t=0) inputs
    float cu = d_U[idx0], cg = d_Gx[idx0], ca = d_Ax[idx0];
    __syncthreads();

    for (int t = 0; t < LSEQ; t++) {
        // prefetch t+1 inputs (independent of h -> overlaps matvec + barrier)
        float nu = 0.0f, ng = 0.0f, na = 0.0f;
        if (t + 1 < LSEQ) {
            size_t id = idx0 + (size_t)(t + 1) * DD;
            nu = d_U[id]; ng = d_Gx[id]; na = d_Ax[id];
        }

        // ---- h-matvec partials: both batches, this thread's K-quarter ----
        const ulonglong2* h0p = (const ulonglong2*)&hs[t & 1][0][q][0];
        const ulonglong2* h1p = (const ulonglong2*)&hs[t & 1][1][q][0];
        ull aG0 = 0ull, aA0 = 0ull, aG1 = 0ull, aA1 = 0ull;
        #pragma unroll
        for (int j = 0; j < 8; j++) {
            ulonglong2 h0 = h0p[j];
            ulonglong2 h1 = h1p[j];
            aG0 = ffma2(wg[2*j  ], h0.x, aG0);
            aA0 = ffma2(wa[2*j  ], h0.x, aA0);
            aG1 = ffma2(wg[2*j  ], h1.x, aG1);
            aA1 = ffma2(wa[2*j  ], h1.x, aA1);
            aG0 = ffma2(wg[2*j+1], h0.y, aG0);
            aA0 = ffma2(wa[2*j+1], h0.y, aA0);
            aG1 = ffma2(wg[2*j+1], h1.y, aG1);
            aA1 = ffma2(wa[2*j+1], h1.y, aA1);
        }
        float2 s;
        s = upk2(aG0); float sG0 = s.x + s.y;
        s = upk2(aA0); float sA0 = s.x + s.y;
        s = upk2(aG1); float sG1 = s.x + s.y;
        s = upk2(aA1); float sA1 = s.x + s.y;

        // ---- reduction over q: 4 shfls total ----
        // step 1 (xor 1): exchange the OTHER batch's partial with mb-partner
        float sendG = mb ? sG0 : sG1;
        float sendA = mb ? sA0 : sA1;
        float rG = __shfl_xor_sync(0xffffffffu, sendG, 1);
        float rA = __shfl_xor_sync(0xffffffffu, sendA, 1);
        float myG = (mb ? sG1 : sG0) + rG;   // my batch, my K-half
        float myA = (mb ? sA1 : sA0) + rA;
        // step 2 (xor 2): fold K-halves (partner has same mb)
        myG += __shfl_xor_sync(0xffffffffu, myG, 2);
        myA += __shfl_xor_sync(0xffffffffu, myA, 2);

        // ---- epilogue (every lane, batch mb) ----
        float g  = tanh_hw(cg + myG);
        float z  = cu * g;
        float a  = ca + myA;
        float m  = fmaxf(a, amax);
        float e  = __expf(m - amax);
        amax = m;
        num  = fmaf(z, e, num);
        den += e;
        float h = tanh_hw(__fdividef(num, den));

        if (q < 2) {
            hs[(t + 1) & 1][mb][o >> 5][o & 31] = h;
            out[idx0 + (size_t)t * DD] = h;
        }

        cu = nu; cg = ng; ca = na;
        __syncthreads();   // publish h(t) for step t+1
    }
}

// ---------------------------------------------------------------------------
// kernel_launch
// Input order (metadata): 0:x  1:s0  2:u_w  3:u_b  4:g_w  5:g_b  6:a_w
// ---------------------------------------------------------------------------
extern "C" void kernel_launch(void* const* d_in, const int* in_sizes, int n_in,
                              void* d_out, int out_size)
{
    const float* x   = (const float*)d_in[0];
    const float* s0  = (const float*)d_in[1];
    const float* u_w = (const float*)d_in[2];
    const float* u_b = (const float*)d_in[3];
    const float* g_w = (const float*)d_in[4];
    const float* g_b = (const float*)d_in[5];
    const float* a_w = (const float*)d_in[6];
    float* out = (float*)d_out;

    cudaFuncSetAttribute(rwa_proj_kernel,
                         cudaFuncAttributeMaxDynamicSharedMemorySize, 131072);

    dim3 pgrid((BSZ * LSEQ) / 128, 3, 1);
    rwa_proj_kernel<<<pgrid, 256, 131072>>>(x, u_w, u_b, g_w, g_b, a_w);

    rwa_rec_kernel<<<BSZ / 2, 512>>>(g_w, a_w, s0, out);
}